// round 14
// baseline (speedup 1.0000x reference)
#include <cuda_runtime.h>
#include <cuda_fp16.h>
#include <cstdint>

#define Bb 2
#define Ss 4096
#define Dd 512
#define Hh 8
#define Ee 64
#define MR (Bb*Ss)          /* 8192 */
#define NQKV (3*Hh*Ee)      /* 1536 */
#define BH (Bb*Hh)          /* 16 */

// Q pre-scale: (1/sqrt(64)) * log2(e)  -> raw ex2 softmax
#define QSCALE 0.1803368801111244f
#define ONESH2 0x3C003C00u

// ---------------- scratch (device globals; no allocations allowed) ----------
__device__ __half g_xa[MR*Dd];
__device__ __half g_wct[NQKV*Dd];
__device__ float g_bcat[NQKV];
__device__ float g_bsum[Dd];
__device__ __half g_wot[Dd*Dd];
__device__ __half g_w1t[Dd*Dd];
__device__ __half g_w2t[Dd*Dd];
__device__ __half g_q[BH*Ss*Ee];
__device__ __half g_k[BH*Ss*Ee];
__device__ __half g_vt[BH*Ee*Ss];
__device__ __half g_ctx[MR*Dd];
__device__ __half g_ya[MR*Dd];
__device__ __half g_ha[MR*Dd];

// ---------------- helpers ----------------------------------------------------
__device__ __forceinline__ uint32_t smem_u32(const void* p){
    uint32_t a;
    asm("{ .reg .u64 t; cvta.to.shared.u64 t, %1; cvt.u32.u64 %0, t; }" : "=r"(a) : "l"(p));
    return a;
}
#define LDSM4(r, a) asm volatile( \
    "ldmatrix.sync.aligned.m8n8.x4.shared.b16 {%0,%1,%2,%3}, [%4];" \
    : "=r"((r)[0]), "=r"((r)[1]), "=r"((r)[2]), "=r"((r)[3]) : "r"(a))
#define MMAF16(c, a0,a1,a2,a3, b0,b1) asm volatile( \
    "mma.sync.aligned.m16n8k16.row.col.f32.f16.f16.f32 " \
    "{%0,%1,%2,%3}, {%4,%5,%6,%7}, {%8,%9}, {%0,%1,%2,%3};" \
    : "+f"((c)[0]), "+f"((c)[1]), "+f"((c)[2]), "+f"((c)[3]) \
    : "r"(a0), "r"(a1), "r"(a2), "r"(a3), "r"(b0), "r"(b1))
#define CP16(dst, src) asm volatile( \
    "cp.async.cg.shared.global [%0], [%1], 16;" :: "r"(dst), "l"(src))
#define CP_COMMIT() asm volatile("cp.async.commit_group;" ::: "memory")

__device__ __forceinline__ uint32_t pack_f16x2(float hi, float lo){
    uint32_t d;
    asm("cvt.rn.f16x2.f32 %0, %1, %2;" : "=r"(d) : "f"(hi), "f"(lo));
    return d;
}
__device__ __forceinline__ uint32_t ex2h2(uint32_t x){
    uint32_t r;
    asm("ex2.approx.f16x2 %0, %1;" : "=r"(r) : "r"(x));
    return r;
}

// ---------------- fused prep kernel ------------------------------------------
__global__ void prep_kernel(const float* __restrict__ x,
                            const float* __restrict__ wq, const float* __restrict__ wk,
                            const float* __restrict__ wv, const float* __restrict__ bq,
                            const float* __restrict__ bk, const float* __restrict__ bv,
                            const float* __restrict__ wo, const float* __restrict__ w1,
                            const float* __restrict__ w2, const float* __restrict__ bo)
{
    int i = blockIdx.x*256 + threadIdx.x;
    if (i < MR*Dd) g_xa[i] = __float2half_rn(x[i]);
    if (i < NQKV*Dd) {
        int n = i >> 9, k = i & 511;
        int proj = n >> 9, hc = n & 511, h = hc >> 6, e = hc & 63;
        const float* w = (proj==0) ? wq : (proj==1 ? wk : wv);
        g_wct[i] = __float2half_rn(w[(h*Dd + k)*Ee + e]);
    }
    if (i < Dd*Dd) {
        int n = i >> 9, k = i & 511;
        int src = k*Dd + n;
        g_wot[i] = __float2half_rn(wo[src]);
        g_w1t[i] = __float2half_rn(w1[src]);
        g_w2t[i] = __float2half_rn(w2[src]);
    }
    if (i < NQKV) {
        int proj = i >> 9, hc = i & 511;
        const float* bb = (proj==0) ? bq : (proj==1 ? bk : bv);
        g_bcat[i] = bb[hc];
    }
    if (i < Dd) {
        float s = 0.f;
        #pragma unroll
        for (int h = 0; h < Hh; h++) s += bo[h*Dd + i];
        g_bsum[i] = s;
    }
}

// ---------------- fp16 GEMM (4 slots, prefetch dist 2, sync per 2 blocks) ----
#define GP 80
#define GS_B 10240
#define GS_SZ 20480
#define G_SMEM (4*GS_SZ)        /* 81920 B */

__global__ __launch_bounds__(256, 2) void gemm_f16_kernel(
    const __half* __restrict__ A, const __half* __restrict__ Bt,
    const float* __restrict__ bias,
    float* __restrict__ C, __half* __restrict__ Ct,
    int M, int N, int K, int mode, int relu)
{
    extern __shared__ char sm[];
    uint32_t sb = smem_u32(sm);
    int t = threadIdx.x, wid = t >> 5, lane = t & 31;
    int mwarp = wid >> 1, nwarp = wid & 1;
    int n0 = blockIdx.x*128, m0 = blockIdx.y*128;
    int l7 = lane & 7;
    int a_blk8 = ((lane >> 3) & 1)*8, a_cofs = ((lane >> 4) & 1)*16;
    int b_blk8 = ((lane >> 4) & 1)*8, b_cofs = ((lane >> 3) & 1)*16;

    const char* pA = (const char*)A;
    const char* pB = (const char*)Bt;

    float acc[2][8][4];
    #pragma unroll
    for (int a = 0; a < 2; a++)
        #pragma unroll
        for (int b = 0; b < 8; b++)
            #pragma unroll
            for (int c = 0; c < 4; c++) acc[a][b][c] = 0.f;

    int nk = K >> 5;   // 32-wide k blocks (16 for K=512)

    auto stage = [&](int kb){
        uint32_t db = sb + (uint32_t)(kb & 3)*GS_SZ;
        #pragma unroll
        for (int j = 0; j < 2; j++) {
            int idx = t + j*256, r = idx >> 2, u = idx & 3;
            uint32_t d = db + r*GP + u*16;
            CP16(d,        pA + ((size_t)(m0 + r)*K + kb*32 + u*8)*2);
            CP16(d + GS_B, pB + ((size_t)(n0 + r)*K + kb*32 + u*8)*2);
        }
    };

    auto body = [&](int kb){
        uint32_t s0 = sb + (uint32_t)(kb & 3)*GS_SZ;
        #pragma unroll
        for (int es = 0; es < 2; es++) {
            uint32_t af[2][4];
            #pragma unroll
            for (int mf = 0; mf < 2; mf++)
                LDSM4(af[mf], s0 + (mwarp*32 + mf*16 + l7 + a_blk8)*GP
                              + es*32 + a_cofs);
            #pragma unroll
            for (int nb = 0; nb < 4; nb++) {
                uint32_t bf4[4];
                LDSM4(bf4, s0 + GS_B + (nwarp*64 + nb*16 + l7 + b_blk8)*GP
                           + es*32 + b_cofs);
                #pragma unroll
                for (int mf = 0; mf < 2; mf++) {
                    MMAF16(acc[mf][2*nb],   af[mf][0],af[mf][1],af[mf][2],af[mf][3], bf4[0], bf4[1]);
                    MMAF16(acc[mf][2*nb+1], af[mf][0],af[mf][1],af[mf][2],af[mf][3], bf4[2], bf4[3]);
                }
            }
        }
    };

    stage(0); stage(1); CP_COMMIT();

    for (int kb = 0; kb < nk; kb += 2) {
        asm volatile("cp.async.wait_group 0;" ::: "memory");
        __syncthreads();
        if (kb + 2 < nk) { stage(kb + 2); stage(kb + 3); CP_COMMIT(); }
        body(kb);
        body(kb + 1);
    }

    // ---- epilogue ----
    #pragma unroll
    for (int mf = 0; mf < 2; mf++) {
        #pragma unroll
        for (int f = 0; f < 8; f++) {
            int c = n0 + nwarp*64 + (f >> 1)*16 + (f & 1)*8 + 2*(lane & 3);
            float b0 = bias[c], b1 = bias[c + 1];
            int r0 = m0 + mwarp*32 + mf*16 + (lane >> 2);
            #pragma unroll
            for (int half = 0; half < 2; half++) {
                int r = r0 + half*8;
                float v0 = acc[mf][f][2*half]     + b0;
                float v1 = acc[mf][f][2*half + 1] + b1;
                if (relu) { v0 = fmaxf(v0, 0.f); v1 = fmaxf(v1, 0.f); }
                if (mode == 0) {
                    *(float2*)&C[(size_t)r*N + c] = make_float2(v0, v1);
                } else if (mode == 1) {
                    ((uint32_t*)Ct)[((size_t)r*N + c) >> 1] = pack_f16x2(v1, v0);
                } else {
                    int n = c;
                    int proj = n >> 9, h = (n >> 6) & 7, e = n & 63;
                    int bh = (r >> 12)*Hh + h;
                    int s = r & 4095;
                    if (proj == 0) { v0 *= QSCALE; v1 *= QSCALE; }
                    if (proj < 2) {
                        __half* dst = (proj ? g_k : g_q);
                        ((uint32_t*)dst)[(((size_t)bh*Ss + s)*Ee + e) >> 1] =
                            pack_f16x2(v1, v0);
                    } else {
                        g_vt[((size_t)bh*Ee + e)*Ss + s]     = __float2half_rn(v0);
                        g_vt[((size_t)bh*Ee + e + 1)*Ss + s] = __float2half_rn(v1);
                    }
                }
            }
        }
    }
}

// ---------------- fp16 flash attention (4 slots, prefetch dist 2) ------------
#define QK_PITCH 144
#define V_PITCH  144
#define ST_K 0
#define ST_V 9216
#define ST_SZ 18432
#define ATT_SMEM (4*ST_SZ)      /* 73728 B */

__device__ __forceinline__ void att_stage(
    uint32_t sbase, const __half* kp, const __half* vp,
    size_t bh, int kt, int t)
{
    uint32_t d0 = sbase + (uint32_t)(kt & 3)*ST_SZ;
    int k0 = kt * 64;
    const char* sk = (const char*)(kp + (bh*Ss + k0)*Ee);
    const char* sv = (const char*)(vp + bh*(size_t)Ee*Ss + k0);
    #pragma unroll
    for (int j = 0; j < 2; j++) {
        int idx = t + j*256, r = idx >> 3, u = idx & 7;
        CP16(d0 + ST_K + r*QK_PITCH + u*16, sk + (size_t)r*128 + u*16);
        CP16(d0 + ST_V + r*V_PITCH + u*16,  sv + (size_t)r*(Ss*2) + u*16);
    }
}

__global__ __launch_bounds__(256, 2) void attn_f16_kernel(
    const __half* __restrict__ qp, const __half* __restrict__ kp,
    const __half* __restrict__ vp, __half* __restrict__ ctx)
{
    extern __shared__ char smem[];
    uint32_t sb = smem_u32(smem);
    int t = threadIdx.x, wid = t >> 5, lane = t & 31;
    int g = lane >> 2, tg = lane & 3;
    size_t bh = blockIdx.y;
    int q0 = blockIdx.x * 128;

    // ---- prologue: stage Q into slot 0, extract fragments ------------------
    {
        const char* sq = (const char*)(qp + (bh*Ss + q0)*Ee);
        #pragma unroll
        for (int j = 0; j < 4; j++) {
            int idx = t + j*256, r = idx >> 3, u = idx & 7;
            CP16(sb + r*QK_PITCH + u*16, sq + (size_t)r*128 + u*16);
        }
        CP_COMMIT();
        asm volatile("cp.async.wait_group 0;" ::: "memory");
        __syncthreads();
    }
    uint32_t qf[4][4];
    {
        int arow = wid*16 + (lane & 7) + ((lane >> 3) & 1)*8;
        int acol = ((lane >> 4) & 1)*16;
        #pragma unroll
        for (int es = 0; es < 4; es++)
            LDSM4(qf[es], sb + arow*QK_PITCH + es*32 + acol);
    }
    __syncthreads();

    att_stage(sb, kp, vp, bh, 0, t);
    att_stage(sb, kp, vp, bh, 1, t); CP_COMMIT();

    float o[8][4];
    #pragma unroll
    for (int i = 0; i < 8; i++)
        #pragma unroll
        for (int j = 0; j < 4; j++) o[i][j] = 0.f;
    float rsacc[4] = {0.f, 0.f, 0.f, 0.f};   // rowsum via ones-MMA

    int l7 = lane & 7, blkr = ((lane >> 4) & 1)*8, blkc = ((lane >> 3) & 1)*16;

    auto body = [&](int kt){
        uint32_t sof = sb + (uint32_t)(kt & 3)*ST_SZ;

        // S = Q K^T
        float s[8][4];
        #pragma unroll
        for (int i = 0; i < 8; i++)
            #pragma unroll
            for (int j = 0; j < 4; j++) s[i][j] = 0.f;

        #pragma unroll
        for (int es = 0; es < 4; es++) {
            #pragma unroll
            for (int kg2 = 0; kg2 < 4; kg2++) {
                uint32_t kb[4];
                LDSM4(kb, sof + ST_K + (kg2*16 + blkr + l7)*QK_PITCH
                          + es*32 + blkc);
                MMAF16(s[2*kg2],   qf[es][0],qf[es][1],qf[es][2],qf[es][3], kb[0], kb[1]);
                MMAF16(s[2*kg2+1], qf[es][0],qf[es][1],qf[es][2],qf[es][3], kb[2], kb[3]);
            }
        }

        // softmax via f16x2 ex2 + rowsum via ones-MMA + PV
        #pragma unroll
        for (int ks = 0; ks < 4; ks++) {
            uint32_t a0 = ex2h2(pack_f16x2(s[2*ks][1],   s[2*ks][0]));
            uint32_t a1 = ex2h2(pack_f16x2(s[2*ks][3],   s[2*ks][2]));
            uint32_t a2 = ex2h2(pack_f16x2(s[2*ks+1][1], s[2*ks+1][0]));
            uint32_t a3 = ex2h2(pack_f16x2(s[2*ks+1][3], s[2*ks+1][2]));
            MMAF16(rsacc, a0, a1, a2, a3, ONESH2, ONESH2);

            #pragma unroll
            for (int eg2 = 0; eg2 < 4; eg2++) {
                uint32_t vb[4];
                LDSM4(vb, sof + ST_V + (eg2*16 + blkr + l7)*V_PITCH
                          + ks*32 + blkc);
                MMAF16(o[2*eg2],   a0, a1, a2, a3, vb[0], vb[1]);
                MMAF16(o[2*eg2+1], a0, a1, a2, a3, vb[2], vb[3]);
            }
        }
    };

    for (int kt = 0; kt < 64; kt += 2) {
        asm volatile("cp.async.wait_group 0;" ::: "memory");
        __syncthreads();
        if (kt + 2 < 64) {
            att_stage(sb, kp, vp, bh, kt + 2, t);
            att_stage(sb, kp, vp, bh, kt + 3, t);
            CP_COMMIT();
        }
        body(kt);
        body(kt + 1);
    }

    // ---- normalize + write ctx (rowsum complete per thread via ones-MMA) ---
    float inv_lo = 1.0f / rsacc[0];
    float inv_hi = 1.0f / rsacc[2];

    int b = (int)(bh >> 3), h = (int)(bh & 7);
    int row0 = q0 + wid*16 + g;
    #pragma unroll
    for (int half = 0; half < 2; half++) {
        int row = row0 + half*8;
        float inv = half ? inv_hi : inv_lo;
        size_t base = ((size_t)b*Ss + row)*Dd + h*Ee;
        #pragma unroll
        for (int j = 0; j < 8; j++) {
            float v0 = o[j][2*half]     * inv;
            float v1 = o[j][2*half + 1] * inv;
            ((uint32_t*)ctx)[(base + j*8 + 2*tg) >> 1] = pack_f16x2(v1, v0);
        }
    }
}

// ---------------- launcher --------------------------------------------------
extern "C" void kernel_launch(void* const* d_in, const int* in_sizes, int n_in,
                              void* d_out, int out_size)
{
    const float* x  = (const float*)d_in[0];
    const float* wq = (const float*)d_in[1];
    const float* bq = (const float*)d_in[2];
    const float* wk = (const float*)d_in[3];
    const float* bk = (const float*)d_in[4];
    const float* wv = (const float*)d_in[5];
    const float* bv = (const float*)d_in[6];
    const float* wo = (const float*)d_in[7];
    const float* bo = (const float*)d_in[8];
    const float* w1 = (const float*)d_in[9];
    const float* b1 = (const float*)d_in[10];
    const float* w2 = (const float*)d_in[11];
    const float* b2 = (const float*)d_in[12];
    float* out = (float*)d_out;

    __half *p_xa, *p_wct, *p_wot, *p_w1t, *p_w2t;
    __half *p_q, *p_k, *p_vt, *p_ctx, *p_ya, *p_ha;
    float *p_bcat, *p_bsum;
    cudaGetSymbolAddress((void**)&p_xa,   g_xa);
    cudaGetSymbolAddress((void**)&p_wct,  g_wct);
    cudaGetSymbolAddress((void**)&p_bcat, g_bcat);
    cudaGetSymbolAddress((void**)&p_bsum, g_bsum);
    cudaGetSymbolAddress((void**)&p_wot,  g_wot);
    cudaGetSymbolAddress((void**)&p_w1t,  g_w1t);
    cudaGetSymbolAddress((void**)&p_w2t,  g_w2t);
    cudaGetSymbolAddress((void**)&p_q,    g_q);
    cudaGetSymbolAddress((void**)&p_k,    g_k);
    cudaGetSymbolAddress((void**)&p_vt,   g_vt);
    cudaGetSymbolAddress((void**)&p_ctx,  g_ctx);
    cudaGetSymbolAddress((void**)&p_ya,   g_ya);
    cudaGetSymbolAddress((void**)&p_ha,   g_ha);

    cudaFuncSetAttribute(attn_f16_kernel,
        cudaFuncAttributeMaxDynamicSharedMemorySize, ATT_SMEM);
    cudaFuncSetAttribute(gemm_f16_kernel,
        cudaFuncAttributeMaxDynamicSharedMemorySize, G_SMEM);

    prep_kernel<<<(MR*Dd + 255)/256, 256>>>(x, wq, wk, wv, bq, bk, bv,
                                            wo, w1, w2, bo);

    gemm_f16_kernel<<<dim3(NQKV/128, MR/128), 256, G_SMEM>>>(
        p_xa, p_wct, p_bcat, nullptr, nullptr, MR, NQKV, Dd, 2, 0);

    attn_f16_kernel<<<dim3(Ss/128, BH), 256, ATT_SMEM>>>(
        p_q, p_k, p_vt, p_ctx);

    gemm_f16_kernel<<<dim3(Dd/128, MR/128), 256, G_SMEM>>>(
        p_ctx, p_wot, p_bsum, nullptr, p_ya, MR, Dd, Dd, 1, 0);

    gemm_f16_kernel<<<dim3(Dd/128, MR/128), 256, G_SMEM>>>(
        p_ya, p_w1t, b1, nullptr, p_ha, MR, Dd, Dd, 1, 1);

    gemm_f16_kernel<<<dim3(Dd/128, MR/128), 256, G_SMEM>>>(
        p_ha, p_w2t, b2, out, nullptr, MR, Dd, Dd, 0, 0);
}

// round 15
// speedup vs baseline: 1.0490x; 1.0490x over previous
#include <cuda_runtime.h>
#include <cuda_fp16.h>
#include <cstdint>

#define Bb 2
#define Ss 4096
#define Dd 512
#define Hh 8
#define Ee 64
#define MR (Bb*Ss)          /* 8192 */
#define NQKV (3*Hh*Ee)      /* 1536 */
#define BH (Bb*Hh)          /* 16 */

// Q pre-scale: (1/sqrt(64)) * log2(e)  -> raw ex2 softmax
#define QSCALE 0.1803368801111244f
#define ONESH2 0x3C003C00u

// ---------------- scratch (device globals; no allocations allowed) ----------
__device__ __half g_xa[MR*Dd];
__device__ __half g_wct[NQKV*Dd];
__device__ float g_bcat[NQKV];
__device__ float g_bsum[Dd];
__device__ __half g_wot[Dd*Dd];
__device__ __half g_w1t[Dd*Dd];
__device__ __half g_w2t[Dd*Dd];
__device__ __half g_q[BH*Ss*Ee];
__device__ __half g_k[BH*Ss*Ee];
__device__ __half g_vt[BH*Ee*Ss];
__device__ __half g_ctx[MR*Dd];
__device__ __half g_ya[MR*Dd];
__device__ __half g_ha[MR*Dd];

// ---------------- helpers ----------------------------------------------------
__device__ __forceinline__ uint32_t smem_u32(const void* p){
    uint32_t a;
    asm("{ .reg .u64 t; cvta.to.shared.u64 t, %1; cvt.u32.u64 %0, t; }" : "=r"(a) : "l"(p));
    return a;
}
#define LDSM4(r, a) asm volatile( \
    "ldmatrix.sync.aligned.m8n8.x4.shared.b16 {%0,%1,%2,%3}, [%4];" \
    : "=r"((r)[0]), "=r"((r)[1]), "=r"((r)[2]), "=r"((r)[3]) : "r"(a))
#define MMAF16(c, a0,a1,a2,a3, b0,b1) asm volatile( \
    "mma.sync.aligned.m16n8k16.row.col.f32.f16.f16.f32 " \
    "{%0,%1,%2,%3}, {%4,%5,%6,%7}, {%8,%9}, {%0,%1,%2,%3};" \
    : "+f"((c)[0]), "+f"((c)[1]), "+f"((c)[2]), "+f"((c)[3]) \
    : "r"(a0), "r"(a1), "r"(a2), "r"(a3), "r"(b0), "r"(b1))
#define CP16(dst, src) asm volatile( \
    "cp.async.cg.shared.global [%0], [%1], 16;" :: "r"(dst), "l"(src))
#define CP_COMMIT() asm volatile("cp.async.commit_group;" ::: "memory")

__device__ __forceinline__ uint32_t pack_f16x2(float hi, float lo){
    uint32_t d;
    asm("cvt.rn.f16x2.f32 %0, %1, %2;" : "=r"(d) : "f"(hi), "f"(lo));
    return d;
}
__device__ __forceinline__ uint32_t ex2h2(uint32_t x){
    uint32_t r;
    asm("ex2.approx.f16x2 %0, %1;" : "=r"(r) : "r"(x));
    return r;
}

// ---------------- fused prep kernel ------------------------------------------
__global__ void prep_kernel(const float* __restrict__ x,
                            const float* __restrict__ wq, const float* __restrict__ wk,
                            const float* __restrict__ wv, const float* __restrict__ bq,
                            const float* __restrict__ bk, const float* __restrict__ bv,
                            const float* __restrict__ wo, const float* __restrict__ w1,
                            const float* __restrict__ w2, const float* __restrict__ bo)
{
    int i = blockIdx.x*256 + threadIdx.x;
    if (i < MR*Dd) g_xa[i] = __float2half_rn(x[i]);
    if (i < NQKV*Dd) {
        int n = i >> 9, k = i & 511;
        int proj = n >> 9, hc = n & 511, h = hc >> 6, e = hc & 63;
        const float* w = (proj==0) ? wq : (proj==1 ? wk : wv);
        g_wct[i] = __float2half_rn(w[(h*Dd + k)*Ee + e]);
    }
    if (i < Dd*Dd) {
        int n = i >> 9, k = i & 511;
        int src = k*Dd + n;
        g_wot[i] = __float2half_rn(wo[src]);
        g_w1t[i] = __float2half_rn(w1[src]);
        g_w2t[i] = __float2half_rn(w2[src]);
    }
    if (i < NQKV) {
        int proj = i >> 9, hc = i & 511;
        const float* bb = (proj==0) ? bq : (proj==1 ? bk : bv);
        g_bcat[i] = bb[hc];
    }
    if (i < Dd) {
        float s = 0.f;
        #pragma unroll
        for (int h = 0; h < Hh; h++) s += bo[h*Dd + i];
        g_bsum[i] = s;
    }
}

// ---------------- fp16 GEMM (unchanged; at HMMA ceiling) ---------------------
#define GP 80
#define GS_B 10240
#define GS_SZ 20480
#define G_SMEM (4*GS_SZ)

__global__ __launch_bounds__(256, 2) void gemm_f16_kernel(
    const __half* __restrict__ A, const __half* __restrict__ Bt,
    const float* __restrict__ bias,
    float* __restrict__ C, __half* __restrict__ Ct,
    int M, int N, int K, int mode, int relu)
{
    extern __shared__ char sm[];
    uint32_t sb = smem_u32(sm);
    int t = threadIdx.x, wid = t >> 5, lane = t & 31;
    int mwarp = wid >> 1, nwarp = wid & 1;
    int n0 = blockIdx.x*128, m0 = blockIdx.y*128;
    int l7 = lane & 7;
    int a_blk8 = ((lane >> 3) & 1)*8, a_cofs = ((lane >> 4) & 1)*16;
    int b_blk8 = ((lane >> 4) & 1)*8, b_cofs = ((lane >> 3) & 1)*16;

    const char* pA = (const char*)A;
    const char* pB = (const char*)Bt;

    float acc[2][8][4];
    #pragma unroll
    for (int a = 0; a < 2; a++)
        #pragma unroll
        for (int b = 0; b < 8; b++)
            #pragma unroll
            for (int c = 0; c < 4; c++) acc[a][b][c] = 0.f;

    int nk = K >> 5;

    auto stage = [&](int kb){
        uint32_t db = sb + (uint32_t)(kb & 3)*GS_SZ;
        #pragma unroll
        for (int j = 0; j < 2; j++) {
            int idx = t + j*256, r = idx >> 2, u = idx & 3;
            uint32_t d = db + r*GP + u*16;
            CP16(d,        pA + ((size_t)(m0 + r)*K + kb*32 + u*8)*2);
            CP16(d + GS_B, pB + ((size_t)(n0 + r)*K + kb*32 + u*8)*2);
        }
    };

    auto body = [&](int kb){
        uint32_t s0 = sb + (uint32_t)(kb & 3)*GS_SZ;
        #pragma unroll
        for (int es = 0; es < 2; es++) {
            uint32_t af[2][4];
            #pragma unroll
            for (int mf = 0; mf < 2; mf++)
                LDSM4(af[mf], s0 + (mwarp*32 + mf*16 + l7 + a_blk8)*GP
                              + es*32 + a_cofs);
            #pragma unroll
            for (int nb = 0; nb < 4; nb++) {
                uint32_t bf4[4];
                LDSM4(bf4, s0 + GS_B + (nwarp*64 + nb*16 + l7 + b_blk8)*GP
                           + es*32 + b_cofs);
                #pragma unroll
                for (int mf = 0; mf < 2; mf++) {
                    MMAF16(acc[mf][2*nb],   af[mf][0],af[mf][1],af[mf][2],af[mf][3], bf4[0], bf4[1]);
                    MMAF16(acc[mf][2*nb+1], af[mf][0],af[mf][1],af[mf][2],af[mf][3], bf4[2], bf4[3]);
                }
            }
        }
    };

    stage(0); stage(1); CP_COMMIT();

    for (int kb = 0; kb < nk; kb += 2) {
        asm volatile("cp.async.wait_group 0;" ::: "memory");
        __syncthreads();
        if (kb + 2 < nk) { stage(kb + 2); stage(kb + 3); CP_COMMIT(); }
        body(kb);
        body(kb + 1);
    }

    #pragma unroll
    for (int mf = 0; mf < 2; mf++) {
        #pragma unroll
        for (int f = 0; f < 8; f++) {
            int c = n0 + nwarp*64 + (f >> 1)*16 + (f & 1)*8 + 2*(lane & 3);
            float b0 = bias[c], b1 = bias[c + 1];
            int r0 = m0 + mwarp*32 + mf*16 + (lane >> 2);
            #pragma unroll
            for (int half = 0; half < 2; half++) {
                int r = r0 + half*8;
                float v0 = acc[mf][f][2*half]     + b0;
                float v1 = acc[mf][f][2*half + 1] + b1;
                if (relu) { v0 = fmaxf(v0, 0.f); v1 = fmaxf(v1, 0.f); }
                if (mode == 0) {
                    *(float2*)&C[(size_t)r*N + c] = make_float2(v0, v1);
                } else if (mode == 1) {
                    ((uint32_t*)Ct)[((size_t)r*N + c) >> 1] = pack_f16x2(v1, v0);
                } else {
                    int n = c;
                    int proj = n >> 9, h = (n >> 6) & 7, e = n & 63;
                    int bh = (r >> 12)*Hh + h;
                    int s = r & 4095;
                    if (proj == 0) { v0 *= QSCALE; v1 *= QSCALE; }
                    if (proj < 2) {
                        __half* dst = (proj ? g_k : g_q);
                        ((uint32_t*)dst)[(((size_t)bh*Ss + s)*Ee + e) >> 1] =
                            pack_f16x2(v1, v0);
                    } else {
                        g_vt[((size_t)bh*Ee + e)*Ss + s]     = __float2half_rn(v0);
                        g_vt[((size_t)bh*Ee + e + 1)*Ss + s] = __float2half_rn(v1);
                    }
                }
            }
        }
    }
}

// ---------------- fp16 flash attention: 4 warps x 32 q-rows, occ 3 ----------
#define QK_PITCH 144
#define V_PITCH  144
#define ST_K 0
#define ST_V 9216
#define ST_SZ 18432
#define ATT_SMEM (4*ST_SZ)      /* 73728 B */

__device__ __forceinline__ void att_stage(
    uint32_t sbase, const __half* kp, const __half* vp,
    size_t bh, int kt, int t)
{
    uint32_t d0 = sbase + (uint32_t)(kt & 3)*ST_SZ;
    int k0 = kt * 64;
    const char* sk = (const char*)(kp + (bh*Ss + k0)*Ee);
    const char* sv = (const char*)(vp + bh*(size_t)Ee*Ss + k0);
    #pragma unroll
    for (int j = 0; j < 4; j++) {
        int idx = t + j*128, r = idx >> 3, u = idx & 7;
        CP16(d0 + ST_K + r*QK_PITCH + u*16, sk + (size_t)r*128 + u*16);
        CP16(d0 + ST_V + r*V_PITCH + u*16,  sv + (size_t)r*(Ss*2) + u*16);
    }
}

__global__ __launch_bounds__(128, 3) void attn_f16_kernel(
    const __half* __restrict__ qp, const __half* __restrict__ kp,
    const __half* __restrict__ vp, __half* __restrict__ ctx)
{
    extern __shared__ char smem[];
    uint32_t sb = smem_u32(smem);
    int t = threadIdx.x, wid = t >> 5, lane = t & 31;
    int g = lane >> 2, tg = lane & 3;
    size_t bh = blockIdx.y;
    int q0 = blockIdx.x * 128;

    // ---- prologue: stage Q (128 rows x 128 B = exactly slot 0) -------------
    {
        const char* sq = (const char*)(qp + (bh*Ss + q0)*Ee);
        #pragma unroll
        for (int j = 0; j < 8; j++) {
            int idx = t + j*128, r = idx >> 3, u = idx & 7;
            CP16(sb + r*QK_PITCH + u*16, sq + (size_t)r*128 + u*16);
        }
        CP_COMMIT();
        asm volatile("cp.async.wait_group 0;" ::: "memory");
        __syncthreads();
    }
    // Q fragments: 2 stacked m16 groups (32 q-rows per warp)
    uint32_t qf[2][4][4];
    {
        int acol = ((lane >> 4) & 1)*16;
        #pragma unroll
        for (int mf = 0; mf < 2; mf++) {
            int arow = wid*32 + mf*16 + (lane & 7) + ((lane >> 3) & 1)*8;
            #pragma unroll
            for (int es = 0; es < 4; es++)
                LDSM4(qf[mf][es], sb + arow*QK_PITCH + es*32 + acol);
        }
    }
    __syncthreads();

    att_stage(sb, kp, vp, bh, 0, t);
    att_stage(sb, kp, vp, bh, 1, t); CP_COMMIT();

    float o[2][8][4];
    #pragma unroll
    for (int mf = 0; mf < 2; mf++)
        #pragma unroll
        for (int i = 0; i < 8; i++)
            #pragma unroll
            for (int j = 0; j < 4; j++) o[mf][i][j] = 0.f;
    float rsacc[2][4] = {{0.f,0.f,0.f,0.f},{0.f,0.f,0.f,0.f}};

    int l7 = lane & 7, blkr = ((lane >> 4) & 1)*8, blkc = ((lane >> 3) & 1)*16;

    auto body = [&](int kt){
        uint32_t sof = sb + (uint32_t)(kt & 3)*ST_SZ;
        // two 32-key halves per 64-key tile
        #pragma unroll
        for (int kh = 0; kh < 2; kh++) {
            float s[2][4][4];
            #pragma unroll
            for (int mf = 0; mf < 2; mf++)
                #pragma unroll
                for (int i = 0; i < 4; i++)
                    #pragma unroll
                    for (int j = 0; j < 4; j++) s[mf][i][j] = 0.f;

            // S = Q K^T for 32 keys
            #pragma unroll
            for (int es = 0; es < 4; es++) {
                #pragma unroll
                for (int kg2 = 0; kg2 < 2; kg2++) {
                    uint32_t kb[4];
                    LDSM4(kb, sof + ST_K + (kh*32 + kg2*16 + blkr + l7)*QK_PITCH
                              + es*32 + blkc);
                    #pragma unroll
                    for (int mf = 0; mf < 2; mf++) {
                        MMAF16(s[mf][2*kg2],   qf[mf][es][0],qf[mf][es][1],qf[mf][es][2],qf[mf][es][3], kb[0], kb[1]);
                        MMAF16(s[mf][2*kg2+1], qf[mf][es][0],qf[mf][es][1],qf[mf][es][2],qf[mf][es][3], kb[2], kb[3]);
                    }
                }
            }

            // softmax (f16x2 ex2) + rowsum ones-MMA + PV for these 32 keys
            #pragma unroll
            for (int ks = 0; ks < 2; ks++) {
                uint32_t a[2][4];
                #pragma unroll
                for (int mf = 0; mf < 2; mf++) {
                    float* sA = s[mf][2*ks];
                    float* sB = s[mf][2*ks+1];
                    a[mf][0] = ex2h2(pack_f16x2(sA[1], sA[0]));
                    a[mf][1] = ex2h2(pack_f16x2(sA[3], sA[2]));
                    a[mf][2] = ex2h2(pack_f16x2(sB[1], sB[0]));
                    a[mf][3] = ex2h2(pack_f16x2(sB[3], sB[2]));
                    MMAF16(rsacc[mf], a[mf][0], a[mf][1], a[mf][2], a[mf][3],
                           ONESH2, ONESH2);
                }
                #pragma unroll
                for (int eg2 = 0; eg2 < 4; eg2++) {
                    uint32_t vb[4];
                    LDSM4(vb, sof + ST_V + (eg2*16 + blkr + l7)*V_PITCH
                              + kh*64 + ks*32 + blkc);
                    #pragma unroll
                    for (int mf = 0; mf < 2; mf++) {
                        MMAF16(o[mf][2*eg2],   a[mf][0],a[mf][1],a[mf][2],a[mf][3], vb[0], vb[1]);
                        MMAF16(o[mf][2*eg2+1], a[mf][0],a[mf][1],a[mf][2],a[mf][3], vb[2], vb[3]);
                    }
                }
            }
        }
    };

    for (int kt = 0; kt < 64; kt += 2) {
        asm volatile("cp.async.wait_group 0;" ::: "memory");
        __syncthreads();
        if (kt + 2 < 64) {
            att_stage(sb, kp, vp, bh, kt + 2, t);
            att_stage(sb, kp, vp, bh, kt + 3, t);
            CP_COMMIT();
        }
        body(kt);
        body(kt + 1);
    }

    // ---- normalize + write ctx ---------------------------------------------
    int b = (int)(bh >> 3), h = (int)(bh & 7);
    #pragma unroll
    for (int mf = 0; mf < 2; mf++) {
        float inv_lo = 1.0f / rsacc[mf][0];
        float inv_hi = 1.0f / rsacc[mf][2];
        int row0 = q0 + wid*32 + mf*16 + g;
        #pragma unroll
        for (int half = 0; half < 2; half++) {
            int row = row0 + half*8;
            float inv = half ? inv_hi : inv_lo;
            size_t base = ((size_t)b*Ss + row)*Dd + h*Ee;
            #pragma unroll
            for (int j = 0; j < 8; j++) {
                float v0 = o[mf][j][2*half]     * inv;
                float v1 = o[mf][j][2*half + 1] * inv;
                ((uint32_t*)ctx)[(base + j*8 + 2*tg) >> 1] = pack_f16x2(v1, v0);
            }
        }
    }
}

// ---------------- launcher --------------------------------------------------
extern "C" void kernel_launch(void* const* d_in, const int* in_sizes, int n_in,
                              void* d_out, int out_size)
{
    const float* x  = (const float*)d_in[0];
    const float* wq = (const float*)d_in[1];
    const float* bq = (const float*)d_in[2];
    const float* wk = (const float*)d_in[3];
    const float* bk = (const float*)d_in[4];
    const float* wv = (const float*)d_in[5];
    const float* bv = (const float*)d_in[6];
    const float* wo = (const float*)d_in[7];
    const float* bo = (const float*)d_in[8];
    const float* w1 = (const float*)d_in[9];
    const float* b1 = (const float*)d_in[10];
    const float* w2 = (const float*)d_in[11];
    const float* b2 = (const float*)d_in[12];
    float* out = (float*)d_out;

    __half *p_xa, *p_wct, *p_wot, *p_w1t, *p_w2t;
    __half *p_q, *p_k, *p_vt, *p_ctx, *p_ya, *p_ha;
    float *p_bcat, *p_bsum;
    cudaGetSymbolAddress((void**)&p_xa,   g_xa);
    cudaGetSymbolAddress((void**)&p_wct,  g_wct);
    cudaGetSymbolAddress((void**)&p_bcat, g_bcat);
    cudaGetSymbolAddress((void**)&p_bsum, g_bsum);
    cudaGetSymbolAddress((void**)&p_wot,  g_wot);
    cudaGetSymbolAddress((void**)&p_w1t,  g_w1t);
    cudaGetSymbolAddress((void**)&p_w2t,  g_w2t);
    cudaGetSymbolAddress((void**)&p_q,    g_q);
    cudaGetSymbolAddress((void**)&p_k,    g_k);
    cudaGetSymbolAddress((void**)&p_vt,   g_vt);
    cudaGetSymbolAddress((void**)&p_ctx,  g_ctx);
    cudaGetSymbolAddress((void**)&p_ya,   g_ya);
    cudaGetSymbolAddress((void**)&p_ha,   g_ha);

    cudaFuncSetAttribute(attn_f16_kernel,
        cudaFuncAttributeMaxDynamicSharedMemorySize, ATT_SMEM);
    cudaFuncSetAttribute(gemm_f16_kernel,
        cudaFuncAttributeMaxDynamicSharedMemorySize, G_SMEM);

    prep_kernel<<<(MR*Dd + 255)/256, 256>>>(x, wq, wk, wv, bq, bk, bv,
                                            wo, w1, w2, bo);

    gemm_f16_kernel<<<dim3(NQKV/128, MR/128), 256, G_SMEM>>>(
        p_xa, p_wct, p_bcat, nullptr, nullptr, MR, NQKV, Dd, 2, 0);

    attn_f16_kernel<<<dim3(Ss/128, BH), 128, ATT_SMEM>>>(
        p_q, p_k, p_vt, p_ctx);

    gemm_f16_kernel<<<dim3(Dd/128, MR/128), 256, G_SMEM>>>(
        p_ctx, p_wot, p_bsum, nullptr, p_ya, MR, Dd, Dd, 1, 0);

    gemm_f16_kernel<<<dim3(Dd/128, MR/128), 256, G_SMEM>>>(
        p_ya, p_w1t, b1, nullptr, p_ha, MR, Dd, Dd, 1, 1);

    gemm_f16_kernel<<<dim3(Dd/128, MR/128), 256, G_SMEM>>>(
        p_ha, p_w2t, b2, out, nullptr, MR, Dd, Dd, 0, 0);
}

// round 16
// speedup vs baseline: 1.0932x; 1.0421x over previous
#include <cuda_runtime.h>
#include <cuda_fp16.h>
#include <cstdint>

#define Bb 2
#define Ss 4096
#define Dd 512
#define Hh 8
#define Ee 64
#define MR (Bb*Ss)          /* 8192 */
#define NQKV (3*Hh*Ee)      /* 1536 */
#define BH (Bb*Hh)          /* 16 */

// Q pre-scale: (1/sqrt(64)) * log2(e)  -> raw ex2 softmax
#define QSCALE 0.1803368801111244f
#define ONESH2 0x3C003C00u

// ---------------- scratch (device globals; no allocations allowed) ----------
__device__ __half g_xa[MR*Dd];
__device__ __half g_wct[NQKV*Dd];
__device__ float g_bcat[NQKV];
__device__ float g_bsum[Dd];
__device__ __half g_wot[Dd*Dd];
__device__ __half g_w1t[Dd*Dd];
__device__ __half g_w2t[Dd*Dd];
__device__ __half g_q[BH*Ss*Ee];
__device__ __half g_k[BH*Ss*Ee];
__device__ __half g_vt[BH*Ee*Ss];
__device__ __half g_ctx[MR*Dd];
__device__ __half g_ya[MR*Dd];
__device__ __half g_ha[MR*Dd];

// ---------------- helpers ----------------------------------------------------
__device__ __forceinline__ uint32_t smem_u32(const void* p){
    uint32_t a;
    asm("{ .reg .u64 t; cvta.to.shared.u64 t, %1; cvt.u32.u64 %0, t; }" : "=r"(a) : "l"(p));
    return a;
}
#define LDSM4(r, a) asm volatile( \
    "ldmatrix.sync.aligned.m8n8.x4.shared.b16 {%0,%1,%2,%3}, [%4];" \
    : "=r"((r)[0]), "=r"((r)[1]), "=r"((r)[2]), "=r"((r)[3]) : "r"(a))
#define MMAF16(c, a0,a1,a2,a3, b0,b1) asm volatile( \
    "mma.sync.aligned.m16n8k16.row.col.f32.f16.f16.f32 " \
    "{%0,%1,%2,%3}, {%4,%5,%6,%7}, {%8,%9}, {%0,%1,%2,%3};" \
    : "+f"((c)[0]), "+f"((c)[1]), "+f"((c)[2]), "+f"((c)[3]) \
    : "r"(a0), "r"(a1), "r"(a2), "r"(a3), "r"(b0), "r"(b1))
// f16 accumulator variant: C = two f16x2 regs (reg0: row g cols 2tg/2tg+1)
#define MMAF16C(c, a0,a1,a2,a3, b0,b1) asm volatile( \
    "mma.sync.aligned.m16n8k16.row.col.f16.f16.f16.f16 " \
    "{%0,%1}, {%2,%3,%4,%5}, {%6,%7}, {%0,%1};" \
    : "+r"((c)[0]), "+r"((c)[1]) \
    : "r"(a0), "r"(a1), "r"(a2), "r"(a3), "r"(b0), "r"(b1))
#define CP16(dst, src) asm volatile( \
    "cp.async.cg.shared.global [%0], [%1], 16;" :: "r"(dst), "l"(src))
#define CP_COMMIT() asm volatile("cp.async.commit_group;" ::: "memory")

__device__ __forceinline__ uint32_t pack_f16x2(float hi, float lo){
    uint32_t d;
    asm("cvt.rn.f16x2.f32 %0, %1, %2;" : "=r"(d) : "f"(hi), "f"(lo));
    return d;
}
__device__ __forceinline__ uint32_t ex2h2(uint32_t x){
    uint32_t r;
    asm("ex2.approx.f16x2 %0, %1;" : "=r"(r) : "r"(x));
    return r;
}

// ---------------- fused prep kernel (x path vectorized 4x) -------------------
__global__ void prep_kernel(const float* __restrict__ x,
                            const float* __restrict__ wq, const float* __restrict__ wk,
                            const float* __restrict__ wv, const float* __restrict__ bq,
                            const float* __restrict__ bk, const float* __restrict__ bv,
                            const float* __restrict__ wo, const float* __restrict__ w1,
                            const float* __restrict__ w2, const float* __restrict__ bo)
{
    int i = blockIdx.x*256 + threadIdx.x;
    if (i < MR*Dd/4) {
        float4 v = ((const float4*)x)[i];
        __half2* d = (__half2*)(g_xa + (size_t)i*4);
        d[0] = __floats2half2_rn(v.x, v.y);
        d[1] = __floats2half2_rn(v.z, v.w);
    }
    if (i < NQKV*Dd) {
        int n = i >> 9, k = i & 511;
        int proj = n >> 9, hc = n & 511, h = hc >> 6, e = hc & 63;
        const float* w = (proj==0) ? wq : (proj==1 ? wk : wv);
        g_wct[i] = __float2half_rn(w[(h*Dd + k)*Ee + e]);
    }
    if (i < Dd*Dd) {
        int n = i >> 9, k = i & 511;
        int src = k*Dd + n;
        g_wot[i] = __float2half_rn(wo[src]);
        g_w1t[i] = __float2half_rn(w1[src]);
        g_w2t[i] = __float2half_rn(w2[src]);
    }
    if (i < NQKV) {
        int proj = i >> 9, hc = i & 511;
        const float* bb = (proj==0) ? bq : (proj==1 ? bk : bv);
        g_bcat[i] = bb[hc];
    }
    if (i < Dd) {
        float s = 0.f;
        #pragma unroll
        for (int h = 0; h < Hh; h++) s += bo[h*Dd + i];
        g_bsum[i] = s;
    }
}

// ---------------- fp16 GEMM (unchanged; at observed ceiling) -----------------
#define GP 80
#define GS_B 10240
#define GS_SZ 20480
#define G_SMEM (4*GS_SZ)

__global__ __launch_bounds__(256, 2) void gemm_f16_kernel(
    const __half* __restrict__ A, const __half* __restrict__ Bt,
    const float* __restrict__ bias,
    float* __restrict__ C, __half* __restrict__ Ct,
    int M, int N, int K, int mode, int relu)
{
    extern __shared__ char sm[];
    uint32_t sb = smem_u32(sm);
    int t = threadIdx.x, wid = t >> 5, lane = t & 31;
    int mwarp = wid >> 1, nwarp = wid & 1;
    int n0 = blockIdx.x*128, m0 = blockIdx.y*128;
    int l7 = lane & 7;
    int a_blk8 = ((lane >> 3) & 1)*8, a_cofs = ((lane >> 4) & 1)*16;
    int b_blk8 = ((lane >> 4) & 1)*8, b_cofs = ((lane >> 3) & 1)*16;

    const char* pA = (const char*)A;
    const char* pB = (const char*)Bt;

    float acc[2][8][4];
    #pragma unroll
    for (int a = 0; a < 2; a++)
        #pragma unroll
        for (int b = 0; b < 8; b++)
            #pragma unroll
            for (int c = 0; c < 4; c++) acc[a][b][c] = 0.f;

    int nk = K >> 5;

    auto stage = [&](int kb){
        uint32_t db = sb + (uint32_t)(kb & 3)*GS_SZ;
        #pragma unroll
        for (int j = 0; j < 2; j++) {
            int idx = t + j*256, r = idx >> 2, u = idx & 3;
            uint32_t d = db + r*GP + u*16;
            CP16(d,        pA + ((size_t)(m0 + r)*K + kb*32 + u*8)*2);
            CP16(d + GS_B, pB + ((size_t)(n0 + r)*K + kb*32 + u*8)*2);
        }
    };

    auto body = [&](int kb){
        uint32_t s0 = sb + (uint32_t)(kb & 3)*GS_SZ;
        #pragma unroll
        for (int es = 0; es < 2; es++) {
            uint32_t af[2][4];
            #pragma unroll
            for (int mf = 0; mf < 2; mf++)
                LDSM4(af[mf], s0 + (mwarp*32 + mf*16 + l7 + a_blk8)*GP
                              + es*32 + a_cofs);
            #pragma unroll
            for (int nb = 0; nb < 4; nb++) {
                uint32_t bf4[4];
                LDSM4(bf4, s0 + GS_B + (nwarp*64 + nb*16 + l7 + b_blk8)*GP
                           + es*32 + b_cofs);
                #pragma unroll
                for (int mf = 0; mf < 2; mf++) {
                    MMAF16(acc[mf][2*nb],   af[mf][0],af[mf][1],af[mf][2],af[mf][3], bf4[0], bf4[1]);
                    MMAF16(acc[mf][2*nb+1], af[mf][0],af[mf][1],af[mf][2],af[mf][3], bf4[2], bf4[3]);
                }
            }
        }
    };

    stage(0); stage(1); CP_COMMIT();

    for (int kb = 0; kb < nk; kb += 2) {
        asm volatile("cp.async.wait_group 0;" ::: "memory");
        __syncthreads();
        if (kb + 2 < nk) { stage(kb + 2); stage(kb + 3); CP_COMMIT(); }
        body(kb);
        body(kb + 1);
    }

    #pragma unroll
    for (int mf = 0; mf < 2; mf++) {
        #pragma unroll
        for (int f = 0; f < 8; f++) {
            int c = n0 + nwarp*64 + (f >> 1)*16 + (f & 1)*8 + 2*(lane & 3);
            float b0 = bias[c], b1 = bias[c + 1];
            int r0 = m0 + mwarp*32 + mf*16 + (lane >> 2);
            #pragma unroll
            for (int half = 0; half < 2; half++) {
                int r = r0 + half*8;
                float v0 = acc[mf][f][2*half]     + b0;
                float v1 = acc[mf][f][2*half + 1] + b1;
                if (relu) { v0 = fmaxf(v0, 0.f); v1 = fmaxf(v1, 0.f); }
                if (mode == 0) {
                    *(float2*)&C[(size_t)r*N + c] = make_float2(v0, v1);
                } else if (mode == 1) {
                    ((uint32_t*)Ct)[((size_t)r*N + c) >> 1] = pack_f16x2(v1, v0);
                } else {
                    int n = c;
                    int proj = n >> 9, h = (n >> 6) & 7, e = n & 63;
                    int bh = (r >> 12)*Hh + h;
                    int s = r & 4095;
                    if (proj == 0) { v0 *= QSCALE; v1 *= QSCALE; }
                    if (proj < 2) {
                        __half* dst = (proj ? g_k : g_q);
                        ((uint32_t*)dst)[(((size_t)bh*Ss + s)*Ee + e) >> 1] =
                            pack_f16x2(v1, v0);
                    } else {
                        g_vt[((size_t)bh*Ee + e)*Ss + s]     = __float2half_rn(v0);
                        g_vt[((size_t)bh*Ee + e + 1)*Ss + s] = __float2half_rn(v1);
                    }
                }
            }
        }
    }
}

// ---------------- fp16 flash attention: 4 warps x 32 q-rows, occ 3,
//                  QK with f16 accumulators (S regs ARE the P A-fragments) ----
#define QK_PITCH 144
#define V_PITCH  144
#define ST_K 0
#define ST_V 9216
#define ST_SZ 18432
#define ATT_SMEM (4*ST_SZ)      /* 73728 B */

__device__ __forceinline__ void att_stage(
    uint32_t sbase, const __half* kp, const __half* vp,
    size_t bh, int kt, int t)
{
    uint32_t d0 = sbase + (uint32_t)(kt & 3)*ST_SZ;
    int k0 = kt * 64;
    const char* sk = (const char*)(kp + (bh*Ss + k0)*Ee);
    const char* sv = (const char*)(vp + bh*(size_t)Ee*Ss + k0);
    #pragma unroll
    for (int j = 0; j < 4; j++) {
        int idx = t + j*128, r = idx >> 3, u = idx & 7;
        CP16(d0 + ST_K + r*QK_PITCH + u*16, sk + (size_t)r*128 + u*16);
        CP16(d0 + ST_V + r*V_PITCH + u*16,  sv + (size_t)r*(Ss*2) + u*16);
    }
}

__global__ __launch_bounds__(128, 3) void attn_f16_kernel(
    const __half* __restrict__ qp, const __half* __restrict__ kp,
    const __half* __restrict__ vp, __half* __restrict__ ctx)
{
    extern __shared__ char smem[];
    uint32_t sb = smem_u32(smem);
    int t = threadIdx.x, wid = t >> 5, lane = t & 31;
    int g = lane >> 2, tg = lane & 3;
    size_t bh = blockIdx.y;
    int q0 = blockIdx.x * 128;

    // ---- prologue: stage Q (128 rows x 128 B = exactly slot 0) -------------
    {
        const char* sq = (const char*)(qp + (bh*Ss + q0)*Ee);
        #pragma unroll
        for (int j = 0; j < 8; j++) {
            int idx = t + j*128, r = idx >> 3, u = idx & 7;
            CP16(sb + r*QK_PITCH + u*16, sq + (size_t)r*128 + u*16);
        }
        CP_COMMIT();
        asm volatile("cp.async.wait_group 0;" ::: "memory");
        __syncthreads();
    }
    uint32_t qf[2][4][4];
    {
        int acol = ((lane >> 4) & 1)*16;
        #pragma unroll
        for (int mf = 0; mf < 2; mf++) {
            int arow = wid*32 + mf*16 + (lane & 7) + ((lane >> 3) & 1)*8;
            #pragma unroll
            for (int es = 0; es < 4; es++)
                LDSM4(qf[mf][es], sb + arow*QK_PITCH + es*32 + acol);
        }
    }
    __syncthreads();

    att_stage(sb, kp, vp, bh, 0, t);
    att_stage(sb, kp, vp, bh, 1, t); CP_COMMIT();

    float o[2][8][4];
    #pragma unroll
    for (int mf = 0; mf < 2; mf++)
        #pragma unroll
        for (int i = 0; i < 8; i++)
            #pragma unroll
            for (int j = 0; j < 4; j++) o[mf][i][j] = 0.f;
    float rsacc[2][4] = {{0.f,0.f,0.f,0.f},{0.f,0.f,0.f,0.f}};

    int l7 = lane & 7, blkr = ((lane >> 4) & 1)*8, blkc = ((lane >> 3) & 1)*16;

    auto body = [&](int kt){
        uint32_t sof = sb + (uint32_t)(kt & 3)*ST_SZ;
        #pragma unroll
        for (int kh = 0; kh < 2; kh++) {
            // S (f16 accum): per mf, 4 n-tiles x 2 f16x2 regs
            uint32_t s[2][4][2];
            #pragma unroll
            for (int mf = 0; mf < 2; mf++)
                #pragma unroll
                for (int i = 0; i < 4; i++) { s[mf][i][0] = 0u; s[mf][i][1] = 0u; }

            #pragma unroll
            for (int es = 0; es < 4; es++) {
                #pragma unroll
                for (int kg2 = 0; kg2 < 2; kg2++) {
                    uint32_t kb[4];
                    LDSM4(kb, sof + ST_K + (kh*32 + kg2*16 + blkr + l7)*QK_PITCH
                              + es*32 + blkc);
                    #pragma unroll
                    for (int mf = 0; mf < 2; mf++) {
                        MMAF16C(s[mf][2*kg2],   qf[mf][es][0],qf[mf][es][1],qf[mf][es][2],qf[mf][es][3], kb[0], kb[1]);
                        MMAF16C(s[mf][2*kg2+1], qf[mf][es][0],qf[mf][es][1],qf[mf][es][2],qf[mf][es][3], kb[2], kb[3]);
                    }
                }
            }

            // softmax: ex2 directly on the f16x2 S regs; rowsum ones-MMA; PV
            #pragma unroll
            for (int ks = 0; ks < 2; ks++) {
                uint32_t a[2][4];
                #pragma unroll
                for (int mf = 0; mf < 2; mf++) {
                    a[mf][0] = ex2h2(s[mf][2*ks][0]);
                    a[mf][1] = ex2h2(s[mf][2*ks][1]);
                    a[mf][2] = ex2h2(s[mf][2*ks+1][0]);
                    a[mf][3] = ex2h2(s[mf][2*ks+1][1]);
                    MMAF16(rsacc[mf], a[mf][0], a[mf][1], a[mf][2], a[mf][3],
                           ONESH2, ONESH2);
                }
                #pragma unroll
                for (int eg2 = 0; eg2 < 4; eg2++) {
                    uint32_t vb[4];
                    LDSM4(vb, sof + ST_V + (eg2*16 + blkr + l7)*V_PITCH
                              + kh*64 + ks*32 + blkc);
                    #pragma unroll
                    for (int mf = 0; mf < 2; mf++) {
                        MMAF16(o[mf][2*eg2],   a[mf][0],a[mf][1],a[mf][2],a[mf][3], vb[0], vb[1]);
                        MMAF16(o[mf][2*eg2+1], a[mf][0],a[mf][1],a[mf][2],a[mf][3], vb[2], vb[3]);
                    }
                }
            }
        }
    };

    for (int kt = 0; kt < 64; kt += 2) {
        asm volatile("cp.async.wait_group 0;" ::: "memory");
        __syncthreads();
        if (kt + 2 < 64) {
            att_stage(sb, kp, vp, bh, kt + 2, t);
            att_stage(sb, kp, vp, bh, kt + 3, t);
            CP_COMMIT();
        }
        body(kt);
        body(kt + 1);
    }

    // ---- normalize + write ctx ---------------------------------------------
    int b = (int)(bh >> 3), h = (int)(bh & 7);
    #pragma unroll
    for (int mf = 0; mf < 2; mf++) {
        float inv_lo = 1.0f / rsacc[mf][0];
        float inv_hi = 1.0f / rsacc[mf][2];
        int row0 = q0 + wid*32 + mf*16 + g;
        #pragma unroll
        for (int half = 0; half < 2; half++) {
            int row = row0 + half*8;
            float inv = half ? inv_hi : inv_lo;
            size_t base = ((size_t)b*Ss + row)*Dd + h*Ee;
            #pragma unroll
            for (int j = 0; j < 8; j++) {
                float v0 = o[mf][j][2*half]     * inv;
                float v1 = o[mf][j][2*half + 1] * inv;
                ((uint32_t*)ctx)[(base + j*8 + 2*tg) >> 1] = pack_f16x2(v1, v0);
            }
        }
    }
}

// ---------------- launcher --------------------------------------------------
extern "C" void kernel_launch(void* const* d_in, const int* in_sizes, int n_in,
                              void* d_out, int out_size)
{
    const float* x  = (const float*)d_in[0];
    const float* wq = (const float*)d_in[1];
    const float* bq = (const float*)d_in[2];
    const float* wk = (const float*)d_in[3];
    const float* bk = (const float*)d_in[4];
    const float* wv = (const float*)d_in[5];
    const float* bv = (const float*)d_in[6];
    const float* wo = (const float*)d_in[7];
    const float* bo = (const float*)d_in[8];
    const float* w1 = (const float*)d_in[9];
    const float* b1 = (const float*)d_in[10];
    const float* w2 = (const float*)d_in[11];
    const float* b2 = (const float*)d_in[12];
    float* out = (float*)d_out;

    __half *p_xa, *p_wct, *p_wot, *p_w1t, *p_w2t;
    __half *p_q, *p_k, *p_vt, *p_ctx, *p_ya, *p_ha;
    float *p_bcat, *p_bsum;
    cudaGetSymbolAddress((void**)&p_xa,   g_xa);
    cudaGetSymbolAddress((void**)&p_wct,  g_wct);
    cudaGetSymbolAddress((void**)&p_bcat, g_bcat);
    cudaGetSymbolAddress((void**)&p_bsum, g_bsum);
    cudaGetSymbolAddress((void**)&p_wot,  g_wot);
    cudaGetSymbolAddress((void**)&p_w1t,  g_w1t);
    cudaGetSymbolAddress((void**)&p_w2t,  g_w2t);
    cudaGetSymbolAddress((void**)&p_q,    g_q);
    cudaGetSymbolAddress((void**)&p_k,    g_k);
    cudaGetSymbolAddress((void**)&p_vt,   g_vt);
    cudaGetSymbolAddress((void**)&p_ctx,  g_ctx);
    cudaGetSymbolAddress((void**)&p_ya,   g_ya);
    cudaGetSymbolAddress((void**)&p_ha,   g_ha);

    cudaFuncSetAttribute(attn_f16_kernel,
        cudaFuncAttributeMaxDynamicSharedMemorySize, ATT_SMEM);
    cudaFuncSetAttribute(gemm_f16_kernel,
        cudaFuncAttributeMaxDynamicSharedMemorySize, G_SMEM);

    prep_kernel<<<(MR*Dd/4 + 255)/256, 256>>>(x, wq, wk, wv, bq, bk, bv,
                                              wo, w1, w2, bo);

    gemm_f16_kernel<<<dim3(NQKV/128, MR/128), 256, G_SMEM>>>(
        p_xa, p_wct, p_bcat, nullptr, nullptr, MR, NQKV, Dd, 2, 0);

    attn_f16_kernel<<<dim3(Ss/128, BH), 128, ATT_SMEM>>>(
        p_q, p_k, p_vt, p_ctx);

    gemm_f16_kernel<<<dim3(Dd/128, MR/128), 256, G_SMEM>>>(
        p_ctx, p_wot, p_bsum, nullptr, p_ya, MR, Dd, Dd, 1, 0);

    gemm_f16_kernel<<<dim3(Dd/128, MR/128), 256, G_SMEM>>>(
        p_ya, p_w1t, b1, nullptr, p_ha, MR, Dd, Dd, 1, 1);

    gemm_f16_kernel<<<dim3(Dd/128, MR/128), 256, G_SMEM>>>(
        p_ha, p_w2t, b2, out, nullptr, MR, Dd, Dd, 0, 0);
}